// round 14
// baseline (speedup 1.0000x reference)
#include <cuda_runtime.h>

#define N_USERC 27094
#define M_SPOTC 42852
#define E_MAXC  2000000

// ── CSR scratch (allocation-free: __device__ globals) ──
__device__ int   g_udeg[N_USERC];
__device__ int   g_sdeg[M_SPOTC];
__device__ float g_urs[N_USERC];       // rsqrt(deg)
__device__ float g_srs[M_SPOTC];
__device__ int   g_uoff[N_USERC + 1];
__device__ int   g_soff[M_SPOTC + 1];
__device__ int   g_ucur[N_USERC];
__device__ int   g_scur[M_SPOTC];
__device__ int2  g_uadj[E_MAXC];       // {spot idx, edge weight} grouped by user
__device__ int2  g_sadj[E_MAXC];       // {user idx, edge weight} grouped by spot

__global__ void zero_kernel() {
    int i = blockIdx.x * blockDim.x + threadIdx.x;
    if (i < N_USERC) g_udeg[i] = 0;
    if (i < M_SPOTC) g_sdeg[i] = 0;
}

__global__ void deg_kernel(const int* __restrict__ es, int E) {
    int e = blockIdx.x * blockDim.x + threadIdx.x;
    if (e < E) {
        atomicAdd(&g_udeg[__ldg(es + e)], 1);
        atomicAdd(&g_sdeg[__ldg(es + E + e)], 1);
    }
}

// Single-pass scan: grid=2 (block 0: users, block 1: spots), 1024 threads.
// Each thread owns a contiguous chunk of ceil(n/1024) degrees. One block-wide
// scan of per-thread sums (2 sync rounds), then each thread writes its chunk's
// exclusive offsets + cursor + fused rsqrt. Replaces the 27/42-iteration
// chunked scan (42.3us measured) and the separate rsqrt kernel.
__global__ void scan_kernel() {
    const int* deg; int* off; int* cur; float* rs; int n;
    if (blockIdx.x == 0) { deg = g_udeg; off = g_uoff; cur = g_ucur; rs = g_urs; n = N_USERC; }
    else                 { deg = g_sdeg; off = g_soff; cur = g_scur; rs = g_srs; n = M_SPOTC; }

    int tid = threadIdx.x, lane = tid & 31, wid = tid >> 5;
    int c = (n + 1023) / 1024;               // chunk size per thread
    int beg = tid * c;
    int end = beg + c; if (end > n) end = n;

    // Local sum of owned chunk
    int sum = 0;
    for (int i = beg; i < end && i >= 0; i++) sum += deg[i];
    if (beg >= n) sum = 0;

    // Block-wide exclusive scan of the 1024 per-thread sums
    __shared__ int wsum[32];
    int x = sum;
    #pragma unroll
    for (int d = 1; d < 32; d <<= 1) {
        int y = __shfl_up_sync(0xffffffffu, x, d);
        if (lane >= d) x += y;
    }
    if (lane == 31) wsum[wid] = x;
    __syncthreads();
    if (wid == 0) {
        int w = wsum[lane], xx = w;
        #pragma unroll
        for (int d = 1; d < 32; d <<= 1) {
            int y = __shfl_up_sync(0xffffffffu, xx, d);
            if (lane >= d) xx += y;
        }
        wsum[lane] = xx - w;                  // exclusive warp offset
    }
    __syncthreads();
    int excl = x - sum + wsum[wid];           // exclusive prefix for this thread

    // Write exclusive offsets, cursors, and fused rsqrt for owned chunk
    int running = excl;
    for (int i = beg; i < end && i >= 0; i++) {
        int d = deg[i];
        off[i] = running;
        cur[i] = running;
        rs[i]  = d ? rsqrtf((float)d) : 0.f;
        running += d;
    }
    if (tid == 1023) off[n] = excl + sum;     // total (last thread's inclusive)
}

// Pack per-edge weight w = urs[u]*srs[s] into the adjacency entries so the
// bandwidth-critical gather never does random scalar lookups.
__global__ void fill_kernel(const int* __restrict__ es, int E) {
    int e = blockIdx.x * blockDim.x + threadIdx.x;
    if (e < E) {
        int u = __ldg(es + e), s = __ldg(es + E + e);
        float w = __ldg(&g_urs[u]) * __ldg(&g_srs[s]);
        int wi = __float_as_int(w);
        g_uadj[atomicAdd(&g_ucur[u], 1)] = make_int2(s, wi);
        g_sadj[atomicAdd(&g_scur[s], 1)] = make_int2(u, wi);
    }
}

// Fused gather: warps [0, N_USERC) do user <- spot, warps [N_USERC, ...) do
// spot <- user. One warp per destination node; lane l owns floats [4l, 4l+4).
// Adjacency (idx, weight) batch-loaded coalesced, broadcast via shfl.
__global__ void __launch_bounds__(256, 8)
gather_kernel(const float4* __restrict__ spot_x,
              const float4* __restrict__ user_x,
              float4* __restrict__ user_out,
              float4* __restrict__ spot_out) {
    int gw = (int)(((long long)blockIdx.x * blockDim.x + threadIdx.x) >> 5);
    int lane = threadIdx.x & 31;

    const int* off; const int2* adj; const float4* src; float4* out;
    int node;

    if (gw < N_USERC) {
        node = gw;
        off = g_uoff; adj = g_uadj; src = spot_x; out = user_out;
    } else if (gw < N_USERC + M_SPOTC) {
        node = gw - N_USERC;
        off = g_soff; adj = g_sadj; src = user_x; out = spot_out;
    } else {
        return;
    }

    int beg = __ldg(&off[node]);
    int end = __ldg(&off[node + 1]);
    float4 acc = make_float4(0.f, 0.f, 0.f, 0.f);

    for (int base = beg; base < end; base += 32) {
        int j = base + lane;
        int2 aw = make_int2(0, 0);
        if (j < end) aw = __ldg(&adj[j]);          // coalesced 8B loads
        int m = end - base; if (m > 32) m = 32;
        if (m == 32) {
            #pragma unroll 8
            for (int t = 0; t < 32; t++) {
                int   s2 = __shfl_sync(0xffffffffu, aw.x, t);
                float ww = __int_as_float(__shfl_sync(0xffffffffu, aw.y, t));
                float4 v = __ldg(src + (size_t)s2 * 32 + lane);
                acc.x += v.x * ww; acc.y += v.y * ww;
                acc.z += v.z * ww; acc.w += v.w * ww;
            }
        } else {
            for (int t = 0; t < m; t++) {
                int   s2 = __shfl_sync(0xffffffffu, aw.x, t);
                float ww = __int_as_float(__shfl_sync(0xffffffffu, aw.y, t));
                float4 v = __ldg(src + (size_t)s2 * 32 + lane);
                acc.x += v.x * ww; acc.y += v.y * ww;
                acc.z += v.z * ww; acc.w += v.w * ww;
            }
        }
    }

    // Streaming store: bypass L1 (keep it for gathers), write-through L2.
    __stcg(&out[(size_t)node * 32 + lane], acc);
}

extern "C" void kernel_launch(void* const* d_in, const int* in_sizes, int n_in,
                              void* d_out, int out_size) {
    const float* spot_x = (const float*)d_in[0];   // [M_SPOT, 128]
    const float* user_x = (const float*)d_in[1];   // [N_USER, 128]
    const int*   es     = (const int*)d_in[2];     // [2, E]

    int m_spot = in_sizes[0] / 128;
    int E      = in_sizes[2] / 2;

    float* out      = (float*)d_out;
    float* spot_out = out;                          // [M_SPOT, 128] first
    float* user_out = out + (size_t)m_spot * 128;   // then [N_USER, 128]

    // CSR build (rsqrt fused into scan)
    zero_kernel <<<(M_SPOTC + 255) / 256, 256>>>();
    deg_kernel  <<<(E + 255) / 256, 256>>>(es, E);
    scan_kernel <<<2, 1024>>>();
    fill_kernel <<<(E + 255) / 256, 256>>>(es, E);

    // Fused gather over both node sets — writes every output element, no memset.
    int total_warps = N_USERC + M_SPOTC;
    gather_kernel<<<(total_warps * 32 + 255) / 256, 256>>>(
        (const float4*)spot_x, (const float4*)user_x,
        (float4*)user_out, (float4*)spot_out);
}

// round 15
// speedup vs baseline: 1.3775x; 1.3775x over previous
#include <cuda_runtime.h>

#define N_USERC 27094
#define M_SPOTC 42852
#define E_MAXC  2000000

#define SEG   2048
#define NB_U  ((N_USERC + SEG - 1) / SEG)   // 14
#define NB_S  ((M_SPOTC + SEG - 1) / SEG)   // 21
#define NB_T  (NB_U + NB_S)                 // 35

// ── CSR scratch (allocation-free: __device__ globals) ──
__device__ int   g_udeg[N_USERC];
__device__ int   g_sdeg[M_SPOTC];
__device__ float g_urs[N_USERC];
__device__ float g_srs[M_SPOTC];
__device__ int   g_uoff[N_USERC + 1];
__device__ int   g_soff[M_SPOTC + 1];
__device__ int   g_ucur[N_USERC];
__device__ int   g_scur[M_SPOTC];
__device__ int   g_psum[NB_T];
__device__ int   g_pscan[NB_T];
__device__ int2  g_uadj[E_MAXC];
__device__ int2  g_sadj[E_MAXC];

__global__ void zero_kernel() {
    int i = blockIdx.x * blockDim.x + threadIdx.x;
    if (i < N_USERC) g_udeg[i] = 0;
    if (i < M_SPOTC) g_sdeg[i] = 0;
}

__global__ void deg_kernel(const int* __restrict__ es, int E) {
    int e = blockIdx.x * blockDim.x + threadIdx.x;
    if (e < E) {
        atomicAdd(&g_udeg[__ldg(es + e)], 1);
        atomicAdd(&g_sdeg[__ldg(es + E + e)], 1);
    }
}

// K1: per-segment sums, coalesced.
__global__ void partial_kernel() {
    int b = blockIdx.x;
    const int* deg; int base, n;
    if (b < NB_U) { deg = g_udeg; base = b * SEG;            n = N_USERC; }
    else          { deg = g_sdeg; base = (b - NB_U) * SEG;   n = M_SPOTC; }
    int end = base + SEG; if (end > n) end = n;
    int tid = threadIdx.x;

    int s = 0;
    for (int i = base + tid; i < end; i += 256) s += deg[i];

    __shared__ int ws[8];
    #pragma unroll
    for (int d = 16; d; d >>= 1) s += __shfl_down_sync(0xffffffffu, s, d);
    if ((tid & 31) == 0) ws[tid >> 5] = s;
    __syncthreads();
    if (tid < 8) {
        s = ws[tid];
        #pragma unroll
        for (int d = 4; d; d >>= 1) s += __shfl_down_sync(0xffu, s, d);
        if (tid == 0) g_psum[b] = s;
    }
}

// K2: scan the 35 segment sums; restart at the user/spot boundary.
__global__ void scan_psum_kernel() {
    __shared__ int sv[64];
    int t = threadIdx.x;
    sv[t] = (t < NB_T) ? g_psum[t] : 0;
    __syncthreads();
    #pragma unroll
    for (int d = 1; d < 64; d <<= 1) {
        int v = sv[t];
        int add = (t >= d) ? sv[t - d] : 0;
        __syncthreads();
        sv[t] = v + add;
        __syncthreads();
    }
    int excl = (t == 0) ? 0 : sv[t - 1];
    int userTot = sv[NB_U - 1];
    if (t < NB_T) g_pscan[t] = (t < NB_U) ? excl : (excl - userTot);
    if (t == 0) {
        g_uoff[N_USERC] = userTot;
        g_soff[M_SPOTC] = sv[NB_T - 1] - userTot;
    }
}

// K3: per-segment exclusive scan in smem, coalesced load + coalesced writes,
// fused rsqrt.
__global__ void write_kernel() {
    int b = blockIdx.x;
    const int* deg; int* off; int* cur; float* rs; int base, n;
    if (b < NB_U) { deg = g_udeg; off = g_uoff; cur = g_ucur; rs = g_urs;
                    base = b * SEG;          n = N_USERC; }
    else          { deg = g_sdeg; off = g_soff; cur = g_scur; rs = g_srs;
                    base = (b - NB_U) * SEG; n = M_SPOTC; }
    int end = base + SEG; if (end > n) end = n;
    int cnt = end - base;
    int tid = threadIdx.x, lane = tid & 31, wid = tid >> 5;

    __shared__ int sdeg[SEG];
    __shared__ int soff[SEG];
    __shared__ int ws[8];

    for (int i = tid; i < cnt; i += 256) sdeg[i] = deg[base + i];
    __syncthreads();

    // per-thread sum of 8 contiguous smem elements
    int tb = tid * 8;
    int s = 0;
    #pragma unroll
    for (int k = 0; k < 8; k++) { int idx = tb + k; if (idx < cnt) s += sdeg[idx]; }

    // block-wide exclusive scan of 256 thread sums
    int x = s;
    #pragma unroll
    for (int d = 1; d < 32; d <<= 1) {
        int y = __shfl_up_sync(0xffffffffu, x, d);
        if (lane >= d) x += y;
    }
    if (lane == 31) ws[wid] = x;
    __syncthreads();
    if (wid == 0 && lane < 8) {
        int w = ws[lane], xx = w;
        #pragma unroll
        for (int d = 1; d < 8; d <<= 1) {
            int y = __shfl_up_sync(0xffu, xx, d);
            if (lane >= d) xx += y;
        }
        ws[lane] = xx - w;
    }
    __syncthreads();

    int run = x - s + ws[wid] + g_pscan[b];   // global exclusive prefix
    #pragma unroll
    for (int k = 0; k < 8; k++) {
        int idx = tb + k;
        if (idx < cnt) { soff[idx] = run; run += sdeg[idx]; }
    }
    __syncthreads();

    // coalesced output writes
    for (int i = tid; i < cnt; i += 256) {
        int o = soff[i], d = sdeg[i];
        off[base + i] = o;
        cur[base + i] = o;
        rs[base + i]  = d ? rsqrtf((float)d) : 0.f;
    }
}

// Pack per-edge weight into adjacency so the gather never does random lookups.
__global__ void fill_kernel(const int* __restrict__ es, int E) {
    int e = blockIdx.x * blockDim.x + threadIdx.x;
    if (e < E) {
        int u = __ldg(es + e), s = __ldg(es + E + e);
        float w = __ldg(&g_urs[u]) * __ldg(&g_srs[s]);
        int wi = __float_as_int(w);
        g_uadj[atomicAdd(&g_ucur[u], 1)] = make_int2(s, wi);
        g_sadj[atomicAdd(&g_scur[s], 1)] = make_int2(u, wi);
    }
}

// Fused gather: one warp per destination node, both directions in one grid.
__global__ void __launch_bounds__(256, 8)
gather_kernel(const float4* __restrict__ spot_x,
              const float4* __restrict__ user_x,
              float4* __restrict__ user_out,
              float4* __restrict__ spot_out) {
    int gw = (int)(((long long)blockIdx.x * blockDim.x + threadIdx.x) >> 5);
    int lane = threadIdx.x & 31;

    const int* off; const int2* adj; const float4* src; float4* out;
    int node;

    if (gw < N_USERC) {
        node = gw;
        off = g_uoff; adj = g_uadj; src = spot_x; out = user_out;
    } else if (gw < N_USERC + M_SPOTC) {
        node = gw - N_USERC;
        off = g_soff; adj = g_sadj; src = user_x; out = spot_out;
    } else {
        return;
    }

    int beg = __ldg(&off[node]);
    int end = __ldg(&off[node + 1]);
    float4 acc = make_float4(0.f, 0.f, 0.f, 0.f);

    for (int base = beg; base < end; base += 32) {
        int j = base + lane;
        int2 aw = make_int2(0, 0);
        if (j < end) aw = __ldg(&adj[j]);
        int m = end - base; if (m > 32) m = 32;
        if (m == 32) {
            #pragma unroll 8
            for (int t = 0; t < 32; t++) {
                int   s2 = __shfl_sync(0xffffffffu, aw.x, t);
                float ww = __int_as_float(__shfl_sync(0xffffffffu, aw.y, t));
                float4 v = __ldg(src + (size_t)s2 * 32 + lane);
                acc.x += v.x * ww; acc.y += v.y * ww;
                acc.z += v.z * ww; acc.w += v.w * ww;
            }
        } else {
            for (int t = 0; t < m; t++) {
                int   s2 = __shfl_sync(0xffffffffu, aw.x, t);
                float ww = __int_as_float(__shfl_sync(0xffffffffu, aw.y, t));
                float4 v = __ldg(src + (size_t)s2 * 32 + lane);
                acc.x += v.x * ww; acc.y += v.y * ww;
                acc.z += v.z * ww; acc.w += v.w * ww;
            }
        }
    }

    __stcg(&out[(size_t)node * 32 + lane], acc);
}

extern "C" void kernel_launch(void* const* d_in, const int* in_sizes, int n_in,
                              void* d_out, int out_size) {
    const float* spot_x = (const float*)d_in[0];   // [M_SPOT, 128]
    const float* user_x = (const float*)d_in[1];   // [N_USER, 128]
    const int*   es     = (const int*)d_in[2];     // [2, E]

    int m_spot = in_sizes[0] / 128;
    int E      = in_sizes[2] / 2;

    float* out      = (float*)d_out;
    float* spot_out = out;
    float* user_out = out + (size_t)m_spot * 128;

    zero_kernel     <<<(M_SPOTC + 255) / 256, 256>>>();
    deg_kernel      <<<(E + 255) / 256, 256>>>(es, E);
    partial_kernel  <<<NB_T, 256>>>();
    scan_psum_kernel<<<1, 64>>>();
    write_kernel    <<<NB_T, 256>>>();
    fill_kernel     <<<(E + 255) / 256, 256>>>(es, E);

    int total_warps = N_USERC + M_SPOTC;
    gather_kernel<<<(total_warps * 32 + 255) / 256, 256>>>(
        (const float4*)spot_x, (const float4*)user_x,
        (float4*)user_out, (float4*)spot_out);
}